// round 12
// baseline (speedup 1.0000x reference)
#include <cuda_runtime.h>
#include <cuda_fp16.h>
#include <cstdint>
#include <cstddef>

// ---------------------------------------------------------------------------
// Problem constants
// ---------------------------------------------------------------------------
#define BATCHN   16384
#define INFEAT   512
#define OUTFEAT  512
#define KSPL     8            // grid_size + spline_order
#define NKNOT    12           // grid_size + 2*order + 1
#define KTOT     4608         // INFEAT*KSPL + INFEAT
#define KBASE    4096         // offset of silu block within K

// GEMM tiling: 128x128 CTA tile, 256 threads, 2 CTAs/SM (best known: R5/R11)
#define BM 128
#define BN 128
#define BK 64                 // 64 halfs = 128 B per smem row
#define NCHUNK (KTOT / BK)    // 72
#define NSTAGE 3
#define A_BYTES (BM * 128)    // 16 KB
#define B_BYTES (BN * 128)    // 16 KB
#define STAGE_BYTES (A_BYTES + B_BYTES)          // 32 KB
#define SMEM_BYTES (1024 + NSTAGE * STAGE_BYTES) // 99328 (incl. align slack)

// ---------------------------------------------------------------------------
// Global scratch (allocation-free rule: __device__ arrays)
// ---------------------------------------------------------------------------
__device__ __align__(256) __half g_A[(size_t)BATCHN * KTOT];   // activations fp16, K-major
__device__ __align__(256) __half g_W[(size_t)OUTFEAT * KTOT];  // packed weights fp16, K-major
__device__ float g_gv[NKNOT];
__device__ float g_rl[3][11];

// ---------------------------------------------------------------------------
// Helpers
// ---------------------------------------------------------------------------
__device__ __forceinline__ uint32_t smem_u32(const void* p) {
    uint32_t a;
    asm("{ .reg .u64 t; cvta.to.shared.u64 t, %1; cvt.u32.u64 %0, t; }"
        : "=r"(a) : "l"(p));
    return a;
}

__device__ __forceinline__ void cp_async16(uint32_t dst, const void* src) {
    asm volatile("cp.async.cg.shared.global [%0], [%1], 16;"
                 :: "r"(dst), "l"(src) : "memory");
}
#define CP_COMMIT() asm volatile("cp.async.commit_group;" ::: "memory")
#define CP_WAIT1()  asm volatile("cp.async.wait_group 1;" ::: "memory")

__device__ __forceinline__ void ldm_x4(uint32_t* r, uint32_t addr) {
    asm volatile("ldmatrix.sync.aligned.m8n8.x4.shared.b16 {%0,%1,%2,%3}, [%4];"
                 : "=r"(r[0]), "=r"(r[1]), "=r"(r[2]), "=r"(r[3]) : "r"(addr));
}

__device__ __forceinline__ void mma16816(float* d, const uint32_t* a, uint32_t b0, uint32_t b1) {
    asm volatile(
        "mma.sync.aligned.m16n8k16.row.col.f32.f16.f16.f32 "
        "{%0,%1,%2,%3}, {%4,%5,%6,%7}, {%8,%9}, {%0,%1,%2,%3};"
        : "+f"(d[0]), "+f"(d[1]), "+f"(d[2]), "+f"(d[3])
        : "r"(a[0]), "r"(a[1]), "r"(a[2]), "r"(a[3]), "r"(b0), "r"(b1));
}

__device__ __forceinline__ uint32_t pack_h2(float a, float b) {
    __half2 h = __floats2half2_rn(a, b);
    return *reinterpret_cast<uint32_t*>(&h);
}

// swizzle within a 128B row: col-byte ^ ((row&7)<<4)
__device__ __forceinline__ uint32_t swz(int row, int colByte) {
    return (uint32_t)(row * 128 + (colByte ^ ((row & 7) << 4)));
}

// ---------------------------------------------------------------------------
// K0: knots + Cox-de-Boor denominator reciprocals
// ---------------------------------------------------------------------------
__global__ void init_tables_kernel(const float* __restrict__ grid) {
    if (threadIdx.x == 0) {
        float gv[NKNOT];
        #pragma unroll
        for (int j = 0; j < NKNOT; j++) { gv[j] = grid[j]; g_gv[j] = gv[j]; }
        #pragma unroll
        for (int k = 1; k <= 3; k++)
            for (int j = 0; j + k < NKNOT; j++)
                g_rl[k - 1][j] = 1.0f / (gv[j + k] - gv[j]);
    }
}

// ---------------------------------------------------------------------------
// K1: pack weights  W'[o][i*8+k] = spline_w*scaler ; W'[o][4096+i] = base_w
// ---------------------------------------------------------------------------
__global__ void __launch_bounds__(256) pack_w_kernel(
    const float* __restrict__ base_w,
    const float* __restrict__ spline_w,
    const float* __restrict__ scaler)
{
    int idx = blockIdx.x * 256 + threadIdx.x;
    int o = idx >> 9, i = idx & 511;
    float sc = scaler[idx];
    const float4* sp = reinterpret_cast<const float4*>(spline_w + (size_t)idx * KSPL);
    float4 s0 = sp[0], s1 = sp[1];
    uint4 v;
    v.x = pack_h2(s0.x * sc, s0.y * sc);
    v.y = pack_h2(s0.z * sc, s0.w * sc);
    v.z = pack_h2(s1.x * sc, s1.y * sc);
    v.w = pack_h2(s1.z * sc, s1.w * sc);
    *reinterpret_cast<uint4*>(g_W + (size_t)o * KTOT + i * KSPL) = v;
    g_W[(size_t)o * KTOT + KBASE + i] = __float2half_rn(base_w[idx]);
}

// ---------------------------------------------------------------------------
// K2: activations, 4 features per thread, closed-form cardinal cubic bases.
// Uniform grid => for x in [g_j, g_j+1), the only nonzero cubic bases are
// indices j-3..j with the cardinal values of t=(x-g_j)/h:
//   B_{j-3}=(1-t)^3/6, B_{j-2}=(4-6t^2+3t^3)/6,
//   B_{j-1}=(1+3t+3t^2-3t^3)/6, B_j=t^3/6
// (~55 ops/elem vs ~120 for full Cox-de-Boor; diff vs reference ~1e-6 rel,
// invisible under fp16 quantization of A).
// ---------------------------------------------------------------------------
__global__ void __launch_bounds__(256) act_kernel(const float* __restrict__ x)
{
    int idx = blockIdx.x * 256 + threadIdx.x;        // 0 .. 16384*128-1
    int b = idx >> 7, i4 = (idx & 127) * 4;          // 4 consecutive features

    float4 xv4 = *reinterpret_cast<const float4*>(x + (size_t)b * INFEAT + i4);
    float xs[4] = {xv4.x, xv4.y, xv4.z, xv4.w};

    float gv[NKNOT];
    #pragma unroll
    for (int j = 0; j < NKNOT; j++) gv[j] = g_gv[j];
    float rl0[11];                                   // exact 1/(g[j+1]-g[j])
    #pragma unroll
    for (int j = 0; j < 11; j++) rl0[j] = g_rl[0][j];
    float inv_h = rl0[5];                            // interior ~1/h for search

    __half sv[4];
    uint4 vout[4];
    #pragma unroll
    for (int e = 0; e < 4; e++) {
        float xv = xs[e];
        sv[e] = __float2half_rn(xv / (1.0f + __expf(-xv)));

        // locate interval j with gv[j] <= xv < gv[j+1]; +-1 corrections fix
        // any rounding from the multiply-based estimate
        int j = (int)floorf((xv - gv[0]) * inv_h);
        j = max(0, min(10, j));
        if (xv < gv[j] && j > 0) j--;
        if (xv >= gv[j + 1] && j < 10) j++;
        bool valid = (xv >= gv[j]) && (xv < gv[j + 1]);  // false outside grid

        float t = (xv - gv[j]) * rl0[j];
        float omt = 1.0f - t;
        float t2 = t * t, t3 = t2 * t;
        const float s6 = 1.0f / 6.0f;
        float v0 = omt * omt * omt * s6;                          // B_{j-3}
        float v1 = (3.0f * t3 - 6.0f * t2 + 4.0f) * s6;           // B_{j-2}
        float v2 = (-3.0f * t3 + 3.0f * t2 + 3.0f * t + 1.0f) * s6; // B_{j-1}
        float v3 = t3 * s6;                                       // B_j

        int base = valid ? (j - 3) : -100;           // invalid -> all zero
        float hb[8];
        #pragma unroll
        for (int s = 0; s < 8; s++) {                // branch-free placement
            int q = s - base;
            float v = (q == 0) ? v0 : (q == 1) ? v1 : (q == 2) ? v2
                    : (q == 3) ? v3 : 0.0f;
            hb[s] = v;
        }
        vout[e].x = pack_h2(hb[0], hb[1]);
        vout[e].y = pack_h2(hb[2], hb[3]);
        vout[e].z = pack_h2(hb[4], hb[5]);
        vout[e].w = pack_h2(hb[6], hb[7]);
    }

    uint4* dst = reinterpret_cast<uint4*>(g_A + (size_t)b * KTOT + i4 * KSPL);
    #pragma unroll
    for (int e = 0; e < 4; e++) dst[e] = vout[e];
    *reinterpret_cast<uint2*>(g_A + (size_t)b * KTOT + KBASE + i4) =
        *reinterpret_cast<uint2*>(sv);
}

// ---------------------------------------------------------------------------
// K3: GEMM out[16384,512] = A @ W'^T   (fp16 in, fp32 accum, mma.sync)
// EXACT R5/R11 structure (best measured: 233us): 256 threads, 8 warps
// (2m x 4n), warp tile 64x32, 3-stage cp.async, ONE __syncthreads per chunk,
// 2 CTAs/SM, sequential K, LDSM-then-MMA per ks. DO NOT TOUCH.
// ---------------------------------------------------------------------------
__device__ __forceinline__ void load_stage(uint32_t sbd, int stage,
                                           const __half* __restrict__ Ag,
                                           const __half* __restrict__ Bg,
                                           int chunk, int tid)
{
    uint32_t a0 = sbd + stage * STAGE_BYTES;
    uint32_t b0 = a0 + A_BYTES;
    const __half* Ac = Ag + chunk * BK;
    const __half* Bc = Bg + chunk * BK;
    #pragma unroll
    for (int t = 0; t < 4; t++) {                    // A: 1024 x 16B granules
        int g = tid + t * 256;
        int r = g >> 3, c = g & 7;
        cp_async16(a0 + swz(r, c * 16), Ac + (size_t)r * KTOT + c * 8);
    }
    #pragma unroll
    for (int t = 0; t < 4; t++) {                    // B: 1024 x 16B granules
        int g = tid + t * 256;
        int r = g >> 3, c = g & 7;
        cp_async16(b0 + swz(r, c * 16), Bc + (size_t)r * KTOT + c * 8);
    }
}

__global__ void __launch_bounds__(256, 2) kan_gemm_kernel(float* __restrict__ out)
{
    extern __shared__ char smem_raw[];
    uint32_t sb_raw = smem_u32(smem_raw);
    uint32_t sbd = (sb_raw + 1023u) & ~1023u;        // swizzle wants clean low bits

    int tid = threadIdx.x, wid = tid >> 5, lid = tid & 31;
    int nt = blockIdx.x, mt = blockIdx.y;
    const __half* Ag = g_A + (size_t)mt * BM * KTOT;
    const __half* Bg = g_W + (size_t)nt * BN * KTOT;

    int wm = (wid >> 2) * 64;                        // warp m offset (2 groups)
    int wn = (wid & 3) * 32;                         // warp n offset (4 groups)

    float d[4][4][4];
    #pragma unroll
    for (int mi = 0; mi < 4; mi++)
        #pragma unroll
        for (int ni = 0; ni < 4; ni++)
            #pragma unroll
            for (int q = 0; q < 4; q++) d[mi][ni][q] = 0.0f;

    // prologue: stages 0,1
    load_stage(sbd, 0, Ag, Bg, 0, tid); CP_COMMIT();
    load_stage(sbd, 1, Ag, Bg, 1, tid); CP_COMMIT();

    // per-lane ldmatrix address components
    // A (no trans): a0..a3 = m0-7/k0-7, m8-15/k0-7, m0-7/k8-15, m8-15/k8-15
    int a_lane_r = lid & 15;
    int a_lane_c = (lid >> 4) << 4;
    // B (no trans; smem [n][k] is Bmat^T for row.col mma):
    //   b-matrices: n0-7/k0-7, n0-7/k8-15, n8-15/k0-7, n8-15/k8-15
    int b_lane_r = ((lid >> 4) << 3) + (lid & 7);
    int b_lane_c = ((lid >> 3) & 1) << 4;

    for (int c = 0; c < NCHUNK; c++) {
        CP_WAIT1();
        __syncthreads();
        // safe: stage (c+2)%3 == (c-1)%3, finished by all warps before the
        // barrier above (load strictly after sync)
        if (c + 2 < NCHUNK) load_stage(sbd, (c + 2) % NSTAGE, Ag, Bg, c + 2, tid);
        CP_COMMIT();                                 // empty group keeps wait invariant

        uint32_t a0 = sbd + (c % NSTAGE) * STAGE_BYTES;
        uint32_t b0 = a0 + A_BYTES;

        #pragma unroll
        for (int ks = 0; ks < 4; ks++) {
            int kb = ks * 32;                        // 16 halfs = 32 bytes
            uint32_t Af[4][4], Bf[2][4];
            #pragma unroll
            for (int mi = 0; mi < 4; mi++) {
                int r = wm + mi * 16 + a_lane_r;
                ldm_x4(Af[mi], a0 + swz(r, kb + a_lane_c));
            }
            #pragma unroll
            for (int L = 0; L < 2; L++) {
                int r = wn + L * 16 + b_lane_r;
                ldm_x4(Bf[L], b0 + swz(r, kb + b_lane_c));
            }
            #pragma unroll
            for (int mi = 0; mi < 4; mi++)
                #pragma unroll
                for (int ni = 0; ni < 4; ni++) {
                    const uint32_t* B2 = Bf[ni >> 1] + ((ni & 1) << 1);
                    mma16816(d[mi][ni], Af[mi], B2[0], B2[1]);
                }
        }
        // no trailing barrier: next iteration's top barrier provides it
    }

    // epilogue: registers -> gmem (no smem involved, no sync needed)
    int gp = lid >> 2, t4 = lid & 3;
    #pragma unroll
    for (int mi = 0; mi < 4; mi++) {
        int row0 = mt * BM + wm + mi * 16 + gp;
        #pragma unroll
        for (int ni = 0; ni < 4; ni++) {
            int col = nt * BN + wn + ni * 8 + t4 * 2;
            float2 v0 = make_float2(d[mi][ni][0], d[mi][ni][1]);
            float2 v1 = make_float2(d[mi][ni][2], d[mi][ni][3]);
            *reinterpret_cast<float2*>(out + (size_t)row0 * OUTFEAT + col)       = v0;
            *reinterpret_cast<float2*>(out + (size_t)(row0 + 8) * OUTFEAT + col) = v1;
        }
    }
}

// ---------------------------------------------------------------------------
// Launch
// ---------------------------------------------------------------------------
extern "C" void kernel_launch(void* const* d_in, const int* in_sizes, int n_in,
                              void* d_out, int out_size)
{
    const float* x        = (const float*)d_in[0];   // (16384, 512)
    const float* grid     = (const float*)d_in[1];   // (512, 12)
    const float* base_w   = (const float*)d_in[2];   // (512, 512)
    const float* spline_w = (const float*)d_in[3];   // (512, 512, 8)
    const float* scaler   = (const float*)d_in[4];   // (512, 512)
    float* out = (float*)d_out;                      // (16384, 512)

    init_tables_kernel<<<1, 32>>>(grid);
    pack_w_kernel<<<(OUTFEAT * INFEAT) / 256, 256>>>(base_w, spline_w, scaler);
    act_kernel<<<(BATCHN * INFEAT / 4) / 256, 256>>>(x);

    cudaFuncSetAttribute(kan_gemm_kernel,
                         cudaFuncAttributeMaxDynamicSharedMemorySize, SMEM_BYTES);
    dim3 g(OUTFEAT / BN, BATCHN / BM);               // (4, 128), n fastest for L2 reuse
    kan_gemm_kernel<<<g, 256, SMEM_BYTES>>>(out);
}

// round 13
// speedup vs baseline: 1.2685x; 1.2685x over previous
#include <cuda_runtime.h>
#include <cuda_fp16.h>
#include <cstdint>
#include <cstddef>

// ---------------------------------------------------------------------------
// Problem constants
// ---------------------------------------------------------------------------
#define BATCHN   16384
#define INFEAT   512
#define OUTFEAT  512
#define KSPL     8            // grid_size + spline_order
#define NKNOT    12           // grid_size + 2*order + 1
#define KTOT     4608         // INFEAT*KSPL + INFEAT
#define KBASE    4096         // offset of silu block within K

// GEMM tiling: 128x128 CTA tile, 256 threads, 2 CTAs/SM (best known: R5/R11)
#define BM 128
#define BN 128
#define BK 64                 // 64 halfs = 128 B per smem row
#define NCHUNK (KTOT / BK)    // 72
#define NSTAGE 3
#define A_BYTES (BM * 128)    // 16 KB
#define B_BYTES (BN * 128)    // 16 KB
#define STAGE_BYTES (A_BYTES + B_BYTES)          // 32 KB
#define SMEM_BYTES (1024 + NSTAGE * STAGE_BYTES) // 99328 (incl. align slack)

// ---------------------------------------------------------------------------
// Global scratch (allocation-free rule: __device__ arrays)
// ---------------------------------------------------------------------------
__device__ __align__(256) __half g_A[(size_t)BATCHN * KTOT];   // activations fp16, K-major
__device__ __align__(256) __half g_W[(size_t)OUTFEAT * KTOT];  // packed weights fp16, K-major
__device__ float g_gv[NKNOT];
__device__ float g_sc[2];                        // [0]=g0, [1]=inv_h (scalars only)

// ---------------------------------------------------------------------------
// Helpers
// ---------------------------------------------------------------------------
__device__ __forceinline__ uint32_t smem_u32(const void* p) {
    uint32_t a;
    asm("{ .reg .u64 t; cvta.to.shared.u64 t, %1; cvt.u32.u64 %0, t; }"
        : "=r"(a) : "l"(p));
    return a;
}

__device__ __forceinline__ void cp_async16(uint32_t dst, const void* src) {
    asm volatile("cp.async.cg.shared.global [%0], [%1], 16;"
                 :: "r"(dst), "l"(src) : "memory");
}
#define CP_COMMIT() asm volatile("cp.async.commit_group;" ::: "memory")
#define CP_WAIT1()  asm volatile("cp.async.wait_group 1;" ::: "memory")

__device__ __forceinline__ void ldm_x4(uint32_t* r, uint32_t addr) {
    asm volatile("ldmatrix.sync.aligned.m8n8.x4.shared.b16 {%0,%1,%2,%3}, [%4];"
                 : "=r"(r[0]), "=r"(r[1]), "=r"(r[2]), "=r"(r[3]) : "r"(addr));
}

__device__ __forceinline__ void mma16816(float* d, const uint32_t* a, uint32_t b0, uint32_t b1) {
    asm volatile(
        "mma.sync.aligned.m16n8k16.row.col.f32.f16.f16.f32 "
        "{%0,%1,%2,%3}, {%4,%5,%6,%7}, {%8,%9}, {%0,%1,%2,%3};"
        : "+f"(d[0]), "+f"(d[1]), "+f"(d[2]), "+f"(d[3])
        : "r"(a[0]), "r"(a[1]), "r"(a[2]), "r"(a[3]), "r"(b0), "r"(b1));
}

__device__ __forceinline__ uint32_t pack_h2(float a, float b) {
    __half2 h = __floats2half2_rn(a, b);
    return *reinterpret_cast<uint32_t*>(&h);
}

// swizzle within a 128B row: col-byte ^ ((row&7)<<4)
__device__ __forceinline__ uint32_t swz(int row, int colByte) {
    return (uint32_t)(row * 128 + (colByte ^ ((row & 7) << 4)));
}

// ---------------------------------------------------------------------------
// K0: scalar constants for the uniform grid
// ---------------------------------------------------------------------------
__global__ void init_tables_kernel(const float* __restrict__ grid) {
    if (threadIdx.x == 0) {
        #pragma unroll
        for (int j = 0; j < NKNOT; j++) g_gv[j] = grid[j];
        g_sc[0] = grid[0];
        g_sc[1] = 1.0f / (grid[1] - grid[0]);    // uniform h
    }
}

// ---------------------------------------------------------------------------
// K1: pack weights  W'[o][i*8+k] = spline_w*scaler ; W'[o][4096+i] = base_w
// ---------------------------------------------------------------------------
__global__ void __launch_bounds__(256) pack_w_kernel(
    const float* __restrict__ base_w,
    const float* __restrict__ spline_w,
    const float* __restrict__ scaler)
{
    int idx = blockIdx.x * 256 + threadIdx.x;
    int o = idx >> 9, i = idx & 511;
    float sc = scaler[idx];
    const float4* sp = reinterpret_cast<const float4*>(spline_w + (size_t)idx * KSPL);
    float4 s0 = sp[0], s1 = sp[1];
    uint4 v;
    v.x = pack_h2(s0.x * sc, s0.y * sc);
    v.y = pack_h2(s0.z * sc, s0.w * sc);
    v.z = pack_h2(s1.x * sc, s1.y * sc);
    v.w = pack_h2(s1.z * sc, s1.w * sc);
    *reinterpret_cast<uint4*>(g_W + (size_t)o * KTOT + i * KSPL) = v;
    g_W[(size_t)o * KTOT + KBASE + i] = __float2half_rn(base_w[idx]);
}

// ---------------------------------------------------------------------------
// K2: activations, 4 features per thread, closed-form cardinal cubic bases.
// ZERO dynamic array indexing (the R12 LMEM bug): interval and local coord
// come from two scalar constants; slot placement is compare-against-j SELs.
// C2 continuity of cubic bases makes ulp-level interval rounding harmless.
// ---------------------------------------------------------------------------
__global__ void __launch_bounds__(256) act_kernel(const float* __restrict__ x)
{
    int idx = blockIdx.x * 256 + threadIdx.x;        // 0 .. 16384*128-1
    int b = idx >> 7, i4 = (idx & 127) * 4;          // 4 consecutive features

    float4 xv4 = *reinterpret_cast<const float4*>(x + (size_t)b * INFEAT + i4);
    float xs[4] = {xv4.x, xv4.y, xv4.z, xv4.w};

    float g0 = g_sc[0], inv_h = g_sc[1];

    __half sv[4];
    uint4 vout[4];
    #pragma unroll
    for (int e = 0; e < 4; e++) {
        float xv = xs[e];
        sv[e] = __float2half_rn(xv / (1.0f + __expf(-xv)));

        float tg = (xv - g0) * inv_h;                // global knot coordinate
        bool valid = (tg >= 0.0f) && (tg < 11.0f);
        float tgc = fminf(fmaxf(tg, 0.0f), 10.999f); // safe conversion range
        int j = (int)tgc;                            // interval index 0..10
        float t = tgc - (float)j;                    // local coord in [0,1)

        float omt = 1.0f - t;
        float t2 = t * t, t3 = t2 * t;
        const float s6 = 1.0f / 6.0f;
        float v0 = omt * omt * omt * s6;                            // slot j-3
        float v1 = (3.0f * t3 - 6.0f * t2 + 4.0f) * s6;             // slot j-2
        float v2 = (-3.0f * t3 + 3.0f * t2 + 3.0f * t + 1.0f) * s6; // slot j-1
        float v3 = t3 * s6;                                         // slot j

        int jm3 = valid ? (j - 3) : -100;            // invalid -> nothing placed
        float hb[8];
        #pragma unroll
        for (int s = 0; s < 8; s++) {                // register-only SEL chain
            float v = 0.0f;
            v = (s == jm3)     ? v0 : v;
            v = (s == jm3 + 1) ? v1 : v;
            v = (s == jm3 + 2) ? v2 : v;
            v = (s == jm3 + 3) ? v3 : v;
            hb[s] = v;
        }
        vout[e].x = pack_h2(hb[0], hb[1]);
        vout[e].y = pack_h2(hb[2], hb[3]);
        vout[e].z = pack_h2(hb[4], hb[5]);
        vout[e].w = pack_h2(hb[6], hb[7]);
    }

    uint4* dst = reinterpret_cast<uint4*>(g_A + (size_t)b * KTOT + i4 * KSPL);
    #pragma unroll
    for (int e = 0; e < 4; e++) dst[e] = vout[e];
    *reinterpret_cast<uint2*>(g_A + (size_t)b * KTOT + KBASE + i4) =
        *reinterpret_cast<uint2*>(sv);
}

// ---------------------------------------------------------------------------
// K3: GEMM out[16384,512] = A @ W'^T   (fp16 in, fp32 accum, mma.sync)
// EXACT R5/R11 structure (best measured: 233us). DO NOT TOUCH.
// ---------------------------------------------------------------------------
__device__ __forceinline__ void load_stage(uint32_t sbd, int stage,
                                           const __half* __restrict__ Ag,
                                           const __half* __restrict__ Bg,
                                           int chunk, int tid)
{
    uint32_t a0 = sbd + stage * STAGE_BYTES;
    uint32_t b0 = a0 + A_BYTES;
    const __half* Ac = Ag + chunk * BK;
    const __half* Bc = Bg + chunk * BK;
    #pragma unroll
    for (int t = 0; t < 4; t++) {                    // A: 1024 x 16B granules
        int g = tid + t * 256;
        int r = g >> 3, c = g & 7;
        cp_async16(a0 + swz(r, c * 16), Ac + (size_t)r * KTOT + c * 8);
    }
    #pragma unroll
    for (int t = 0; t < 4; t++) {                    // B: 1024 x 16B granules
        int g = tid + t * 256;
        int r = g >> 3, c = g & 7;
        cp_async16(b0 + swz(r, c * 16), Bc + (size_t)r * KTOT + c * 8);
    }
}

__global__ void __launch_bounds__(256, 2) kan_gemm_kernel(float* __restrict__ out)
{
    extern __shared__ char smem_raw[];
    uint32_t sb_raw = smem_u32(smem_raw);
    uint32_t sbd = (sb_raw + 1023u) & ~1023u;        // swizzle wants clean low bits

    int tid = threadIdx.x, wid = tid >> 5, lid = tid & 31;
    int nt = blockIdx.x, mt = blockIdx.y;
    const __half* Ag = g_A + (size_t)mt * BM * KTOT;
    const __half* Bg = g_W + (size_t)nt * BN * KTOT;

    int wm = (wid >> 2) * 64;                        // warp m offset (2 groups)
    int wn = (wid & 3) * 32;                         // warp n offset (4 groups)

    float d[4][4][4];
    #pragma unroll
    for (int mi = 0; mi < 4; mi++)
        #pragma unroll
        for (int ni = 0; ni < 4; ni++)
            #pragma unroll
            for (int q = 0; q < 4; q++) d[mi][ni][q] = 0.0f;

    // prologue: stages 0,1
    load_stage(sbd, 0, Ag, Bg, 0, tid); CP_COMMIT();
    load_stage(sbd, 1, Ag, Bg, 1, tid); CP_COMMIT();

    // per-lane ldmatrix address components
    // A (no trans): a0..a3 = m0-7/k0-7, m8-15/k0-7, m0-7/k8-15, m8-15/k8-15
    int a_lane_r = lid & 15;
    int a_lane_c = (lid >> 4) << 4;
    // B (no trans; smem [n][k] is Bmat^T for row.col mma):
    //   b-matrices: n0-7/k0-7, n0-7/k8-15, n8-15/k0-7, n8-15/k8-15
    int b_lane_r = ((lid >> 4) << 3) + (lid & 7);
    int b_lane_c = ((lid >> 3) & 1) << 4;

    for (int c = 0; c < NCHUNK; c++) {
        CP_WAIT1();
        __syncthreads();
        // safe: stage (c+2)%3 == (c-1)%3, finished by all warps before the
        // barrier above (load strictly after sync)
        if (c + 2 < NCHUNK) load_stage(sbd, (c + 2) % NSTAGE, Ag, Bg, c + 2, tid);
        CP_COMMIT();                                 // empty group keeps wait invariant

        uint32_t a0 = sbd + (c % NSTAGE) * STAGE_BYTES;
        uint32_t b0 = a0 + A_BYTES;

        #pragma unroll
        for (int ks = 0; ks < 4; ks++) {
            int kb = ks * 32;                        // 16 halfs = 32 bytes
            uint32_t Af[4][4], Bf[2][4];
            #pragma unroll
            for (int mi = 0; mi < 4; mi++) {
                int r = wm + mi * 16 + a_lane_r;
                ldm_x4(Af[mi], a0 + swz(r, kb + a_lane_c));
            }
            #pragma unroll
            for (int L = 0; L < 2; L++) {
                int r = wn + L * 16 + b_lane_r;
                ldm_x4(Bf[L], b0 + swz(r, kb + b_lane_c));
            }
            #pragma unroll
            for (int mi = 0; mi < 4; mi++)
                #pragma unroll
                for (int ni = 0; ni < 4; ni++) {
                    const uint32_t* B2 = Bf[ni >> 1] + ((ni & 1) << 1);
                    mma16816(d[mi][ni], Af[mi], B2[0], B2[1]);
                }
        }
        // no trailing barrier: next iteration's top barrier provides it
    }

    // epilogue: registers -> gmem (no smem involved, no sync needed)
    int gp = lid >> 2, t4 = lid & 3;
    #pragma unroll
    for (int mi = 0; mi < 4; mi++) {
        int row0 = mt * BM + wm + mi * 16 + gp;
        #pragma unroll
        for (int ni = 0; ni < 4; ni++) {
            int col = nt * BN + wn + ni * 8 + t4 * 2;
            float2 v0 = make_float2(d[mi][ni][0], d[mi][ni][1]);
            float2 v1 = make_float2(d[mi][ni][2], d[mi][ni][3]);
            *reinterpret_cast<float2*>(out + (size_t)row0 * OUTFEAT + col)       = v0;
            *reinterpret_cast<float2*>(out + (size_t)(row0 + 8) * OUTFEAT + col) = v1;
        }
    }
}

// ---------------------------------------------------------------------------
// Launch
// ---------------------------------------------------------------------------
extern "C" void kernel_launch(void* const* d_in, const int* in_sizes, int n_in,
                              void* d_out, int out_size)
{
    const float* x        = (const float*)d_in[0];   // (16384, 512)
    const float* grid     = (const float*)d_in[1];   // (512, 12)
    const float* base_w   = (const float*)d_in[2];   // (512, 512)
    const float* spline_w = (const float*)d_in[3];   // (512, 512, 8)
    const float* scaler   = (const float*)d_in[4];   // (512, 512)
    float* out = (float*)d_out;                      // (16384, 512)

    init_tables_kernel<<<1, 32>>>(grid);
    pack_w_kernel<<<(OUTFEAT * INFEAT) / 256, 256>>>(base_w, spline_w, scaler);
    act_kernel<<<(BATCHN * INFEAT / 4) / 256, 256>>>(x);

    cudaFuncSetAttribute(kan_gemm_kernel,
                         cudaFuncAttributeMaxDynamicSharedMemorySize, SMEM_BYTES);
    dim3 g(OUTFEAT / BN, BATCHN / BM);               // (4, 128), n fastest for L2 reuse
    kan_gemm_kernel<<<g, 256, SMEM_BYTES>>>(out);
}

// round 14
// speedup vs baseline: 1.2750x; 1.0051x over previous
#include <cuda_runtime.h>
#include <cuda_fp16.h>
#include <cstdint>
#include <cstddef>

// ---------------------------------------------------------------------------
// Problem constants
// ---------------------------------------------------------------------------
#define BATCHN   16384
#define INFEAT   512
#define OUTFEAT  512
#define KSPL     8            // grid_size + spline_order
#define NKNOT    12           // grid_size + 2*order + 1
#define KTOT     4608         // INFEAT*KSPL + INFEAT
#define KBASE    4096         // offset of silu block within K

// GEMM tiling: 128x128 CTA tile, 256 threads, 2 CTAs/SM (best known: R5/R11)
#define BM 128
#define BN 128
#define BK 64                 // 64 halfs = 128 B per smem row
#define NCHUNK (KTOT / BK)    // 72
#define NSTAGE 3
#define A_BYTES (BM * 128)    // 16 KB
#define B_BYTES (BN * 128)    // 16 KB
#define STAGE_BYTES (A_BYTES + B_BYTES)          // 32 KB
#define SMEM_BYTES (1024 + NSTAGE * STAGE_BYTES) // 99328 (incl. align slack)

// prep kernel block split
#define PACK_BLOCKS ((OUTFEAT * INFEAT) / 256)           // 1024
#define ACT_BLOCKS  ((BATCHN * INFEAT / 4) / 256)        // 8192
#define PREP_BLOCKS (PACK_BLOCKS + ACT_BLOCKS)

// ---------------------------------------------------------------------------
// Global scratch (allocation-free rule: __device__ arrays)
// ---------------------------------------------------------------------------
__device__ __align__(256) __half g_A[(size_t)BATCHN * KTOT];   // activations fp16, K-major
__device__ __align__(256) __half g_W[(size_t)OUTFEAT * KTOT];  // packed weights fp16, K-major

// ---------------------------------------------------------------------------
// Helpers
// ---------------------------------------------------------------------------
__device__ __forceinline__ uint32_t smem_u32(const void* p) {
    uint32_t a;
    asm("{ .reg .u64 t; cvta.to.shared.u64 t, %1; cvt.u32.u64 %0, t; }"
        : "=r"(a) : "l"(p));
    return a;
}

__device__ __forceinline__ void cp_async16(uint32_t dst, const void* src) {
    asm volatile("cp.async.cg.shared.global [%0], [%1], 16;"
                 :: "r"(dst), "l"(src) : "memory");
}
#define CP_COMMIT() asm volatile("cp.async.commit_group;" ::: "memory")
#define CP_WAIT1()  asm volatile("cp.async.wait_group 1;" ::: "memory")

__device__ __forceinline__ void ldm_x4(uint32_t* r, uint32_t addr) {
    asm volatile("ldmatrix.sync.aligned.m8n8.x4.shared.b16 {%0,%1,%2,%3}, [%4];"
                 : "=r"(r[0]), "=r"(r[1]), "=r"(r[2]), "=r"(r[3]) : "r"(addr));
}

__device__ __forceinline__ void mma16816(float* d, const uint32_t* a, uint32_t b0, uint32_t b1) {
    asm volatile(
        "mma.sync.aligned.m16n8k16.row.col.f32.f16.f16.f32 "
        "{%0,%1,%2,%3}, {%4,%5,%6,%7}, {%8,%9}, {%0,%1,%2,%3};"
        : "+f"(d[0]), "+f"(d[1]), "+f"(d[2]), "+f"(d[3])
        : "r"(a[0]), "r"(a[1]), "r"(a[2]), "r"(a[3]), "r"(b0), "r"(b1));
}

__device__ __forceinline__ uint32_t pack_h2(float a, float b) {
    __half2 h = __floats2half2_rn(a, b);
    return *reinterpret_cast<uint32_t*>(&h);
}

// swizzle within a 128B row: col-byte ^ ((row&7)<<4)
__device__ __forceinline__ uint32_t swz(int row, int colByte) {
    return (uint32_t)(row * 128 + (colByte ^ ((row & 7) << 4)));
}

// ---------------------------------------------------------------------------
// K1: fused prep — pack W (blocks [0, PACK_BLOCKS)) and build A (the rest),
// running concurrently in one launch. Act path derives grid scalars directly
// from gmem (broadcast loads), so no init kernel is needed.
// ---------------------------------------------------------------------------
__global__ void __launch_bounds__(256) prep_kernel(
    const float* __restrict__ x,
    const float* __restrict__ grid,
    const float* __restrict__ base_w,
    const float* __restrict__ spline_w,
    const float* __restrict__ scaler)
{
    if (blockIdx.x < PACK_BLOCKS) {
        // ---- pack W'[o][i*8+k] = spline_w*scaler ; W'[o][4096+i] = base_w
        int idx = blockIdx.x * 256 + threadIdx.x;
        int o = idx >> 9, i = idx & 511;
        float sc = scaler[idx];
        const float4* sp = reinterpret_cast<const float4*>(spline_w + (size_t)idx * KSPL);
        float4 s0 = sp[0], s1 = sp[1];
        uint4 v;
        v.x = pack_h2(s0.x * sc, s0.y * sc);
        v.y = pack_h2(s0.z * sc, s0.w * sc);
        v.z = pack_h2(s1.x * sc, s1.y * sc);
        v.w = pack_h2(s1.z * sc, s1.w * sc);
        *reinterpret_cast<uint4*>(g_W + (size_t)o * KTOT + i * KSPL) = v;
        g_W[(size_t)o * KTOT + KBASE + i] = __float2half_rn(base_w[idx]);
        return;
    }

    // ---- act: 4 features per thread, closed-form cardinal cubic bases
    // (zero dynamic register indexing; see R12 post-mortem)
    int idx = (blockIdx.x - PACK_BLOCKS) * 256 + threadIdx.x;  // 0..16384*128-1
    int b = idx >> 7, i4 = (idx & 127) * 4;

    float4 xv4 = *reinterpret_cast<const float4*>(x + (size_t)b * INFEAT + i4);
    float xs[4] = {xv4.x, xv4.y, xv4.z, xv4.w};

    float g0 = __ldg(&grid[0]);
    float inv_h = 1.0f / (__ldg(&grid[1]) - g0);     // uniform grid

    __half sv[4];
    uint4 vout[4];
    #pragma unroll
    for (int e = 0; e < 4; e++) {
        float xv = xs[e];
        sv[e] = __float2half_rn(xv / (1.0f + __expf(-xv)));

        float tg = (xv - g0) * inv_h;                // global knot coordinate
        bool valid = (tg >= 0.0f) && (tg < 11.0f);
        float tgc = fminf(fmaxf(tg, 0.0f), 10.999f);
        int j = (int)tgc;                            // interval index 0..10
        float t = tgc - (float)j;                    // local coord in [0,1)

        float omt = 1.0f - t;
        float t2 = t * t, t3 = t2 * t;
        const float s6 = 1.0f / 6.0f;
        float v0 = omt * omt * omt * s6;                            // slot j-3
        float v1 = (3.0f * t3 - 6.0f * t2 + 4.0f) * s6;             // slot j-2
        float v2 = (-3.0f * t3 + 3.0f * t2 + 3.0f * t + 1.0f) * s6; // slot j-1
        float v3 = t3 * s6;                                         // slot j

        int jm3 = valid ? (j - 3) : -100;            // invalid -> all zero
        float hb[8];
        #pragma unroll
        for (int s = 0; s < 8; s++) {                // register-only SEL chain
            float v = 0.0f;
            v = (s == jm3)     ? v0 : v;
            v = (s == jm3 + 1) ? v1 : v;
            v = (s == jm3 + 2) ? v2 : v;
            v = (s == jm3 + 3) ? v3 : v;
            hb[s] = v;
        }
        vout[e].x = pack_h2(hb[0], hb[1]);
        vout[e].y = pack_h2(hb[2], hb[3]);
        vout[e].z = pack_h2(hb[4], hb[5]);
        vout[e].w = pack_h2(hb[6], hb[7]);
    }

    uint4* dst = reinterpret_cast<uint4*>(g_A + (size_t)b * KTOT + i4 * KSPL);
    #pragma unroll
    for (int e = 0; e < 4; e++) dst[e] = vout[e];
    *reinterpret_cast<uint2*>(g_A + (size_t)b * KTOT + KBASE + i4) =
        *reinterpret_cast<uint2*>(sv);
}

// ---------------------------------------------------------------------------
// K3: GEMM out[16384,512] = A @ W'^T   (fp16 in, fp32 accum, mma.sync)
// EXACT R5/R11/R13 structure (best measured: 233-235us). DO NOT TOUCH.
// ---------------------------------------------------------------------------
__device__ __forceinline__ void load_stage(uint32_t sbd, int stage,
                                           const __half* __restrict__ Ag,
                                           const __half* __restrict__ Bg,
                                           int chunk, int tid)
{
    uint32_t a0 = sbd + stage * STAGE_BYTES;
    uint32_t b0 = a0 + A_BYTES;
    const __half* Ac = Ag + chunk * BK;
    const __half* Bc = Bg + chunk * BK;
    #pragma unroll
    for (int t = 0; t < 4; t++) {                    // A: 1024 x 16B granules
        int g = tid + t * 256;
        int r = g >> 3, c = g & 7;
        cp_async16(a0 + swz(r, c * 16), Ac + (size_t)r * KTOT + c * 8);
    }
    #pragma unroll
    for (int t = 0; t < 4; t++) {                    // B: 1024 x 16B granules
        int g = tid + t * 256;
        int r = g >> 3, c = g & 7;
        cp_async16(b0 + swz(r, c * 16), Bc + (size_t)r * KTOT + c * 8);
    }
}

__global__ void __launch_bounds__(256, 2) kan_gemm_kernel(float* __restrict__ out)
{
    extern __shared__ char smem_raw[];
    uint32_t sb_raw = smem_u32(smem_raw);
    uint32_t sbd = (sb_raw + 1023u) & ~1023u;        // swizzle wants clean low bits

    int tid = threadIdx.x, wid = tid >> 5, lid = tid & 31;
    int nt = blockIdx.x, mt = blockIdx.y;
    const __half* Ag = g_A + (size_t)mt * BM * KTOT;
    const __half* Bg = g_W + (size_t)nt * BN * KTOT;

    int wm = (wid >> 2) * 64;                        // warp m offset (2 groups)
    int wn = (wid & 3) * 32;                         // warp n offset (4 groups)

    float d[4][4][4];
    #pragma unroll
    for (int mi = 0; mi < 4; mi++)
        #pragma unroll
        for (int ni = 0; ni < 4; ni++)
            #pragma unroll
            for (int q = 0; q < 4; q++) d[mi][ni][q] = 0.0f;

    // prologue: stages 0,1
    load_stage(sbd, 0, Ag, Bg, 0, tid); CP_COMMIT();
    load_stage(sbd, 1, Ag, Bg, 1, tid); CP_COMMIT();

    // per-lane ldmatrix address components
    // A (no trans): a0..a3 = m0-7/k0-7, m8-15/k0-7, m0-7/k8-15, m8-15/k8-15
    int a_lane_r = lid & 15;
    int a_lane_c = (lid >> 4) << 4;
    // B (no trans; smem [n][k] is Bmat^T for row.col mma):
    //   b-matrices: n0-7/k0-7, n0-7/k8-15, n8-15/k0-7, n8-15/k8-15
    int b_lane_r = ((lid >> 4) << 3) + (lid & 7);
    int b_lane_c = ((lid >> 3) & 1) << 4;

    for (int c = 0; c < NCHUNK; c++) {
        CP_WAIT1();
        __syncthreads();
        // safe: stage (c+2)%3 == (c-1)%3, finished by all warps before the
        // barrier above (load strictly after sync)
        if (c + 2 < NCHUNK) load_stage(sbd, (c + 2) % NSTAGE, Ag, Bg, c + 2, tid);
        CP_COMMIT();                                 // empty group keeps wait invariant

        uint32_t a0 = sbd + (c % NSTAGE) * STAGE_BYTES;
        uint32_t b0 = a0 + A_BYTES;

        #pragma unroll
        for (int ks = 0; ks < 4; ks++) {
            int kb = ks * 32;                        // 16 halfs = 32 bytes
            uint32_t Af[4][4], Bf[2][4];
            #pragma unroll
            for (int mi = 0; mi < 4; mi++) {
                int r = wm + mi * 16 + a_lane_r;
                ldm_x4(Af[mi], a0 + swz(r, kb + a_lane_c));
            }
            #pragma unroll
            for (int L = 0; L < 2; L++) {
                int r = wn + L * 16 + b_lane_r;
                ldm_x4(Bf[L], b0 + swz(r, kb + b_lane_c));
            }
            #pragma unroll
            for (int mi = 0; mi < 4; mi++)
                #pragma unroll
                for (int ni = 0; ni < 4; ni++) {
                    const uint32_t* B2 = Bf[ni >> 1] + ((ni & 1) << 1);
                    mma16816(d[mi][ni], Af[mi], B2[0], B2[1]);
                }
        }
        // no trailing barrier: next iteration's top barrier provides it
    }

    // epilogue: registers -> gmem (no smem involved, no sync needed)
    int gp = lid >> 2, t4 = lid & 3;
    #pragma unroll
    for (int mi = 0; mi < 4; mi++) {
        int row0 = mt * BM + wm + mi * 16 + gp;
        #pragma unroll
        for (int ni = 0; ni < 4; ni++) {
            int col = nt * BN + wn + ni * 8 + t4 * 2;
            float2 v0 = make_float2(d[mi][ni][0], d[mi][ni][1]);
            float2 v1 = make_float2(d[mi][ni][2], d[mi][ni][3]);
            *reinterpret_cast<float2*>(out + (size_t)row0 * OUTFEAT + col)       = v0;
            *reinterpret_cast<float2*>(out + (size_t)(row0 + 8) * OUTFEAT + col) = v1;
        }
    }
}

// ---------------------------------------------------------------------------
// Launch: ONE prep kernel (pack + act fused, concurrent) + GEMM
// ---------------------------------------------------------------------------
extern "C" void kernel_launch(void* const* d_in, const int* in_sizes, int n_in,
                              void* d_out, int out_size)
{
    const float* x        = (const float*)d_in[0];   // (16384, 512)
    const float* grid     = (const float*)d_in[1];   // (512, 12)
    const float* base_w   = (const float*)d_in[2];   // (512, 512)
    const float* spline_w = (const float*)d_in[3];   // (512, 512, 8)
    const float* scaler   = (const float*)d_in[4];   // (512, 512)
    float* out = (float*)d_out;                      // (16384, 512)

    prep_kernel<<<PREP_BLOCKS, 256>>>(x, grid, base_w, spline_w, scaler);

    cudaFuncSetAttribute(kan_gemm_kernel,
                         cudaFuncAttributeMaxDynamicSharedMemorySize, SMEM_BYTES);
    dim3 g(OUTFEAT / BN, BATCHN / BM);               // (4, 128), n fastest for L2 reuse
    kan_gemm_kernel<<<g, 256, SMEM_BYTES>>>(out);
}